// round 7
// baseline (speedup 1.0000x reference)
#include <cuda_runtime.h>
#include <math.h>

#define Bsz 16
#define Ssz 1024
#define Hsz 768
#define NHs 12
#define Dh  64
#define FFs 3072
#define NB  512
#define NT  256

// ---------------- scratch (device globals; 128B-aligned, sizes = 128B multiples) ----
__device__ __align__(128) float d_q0p[24*Bsz*Hsz];
__device__ __align__(128) float d_u[Bsz*NHs*Hsz];        // prescaled by 1/8
__device__ __align__(128) float d_qbk[Bsz*NHs+16];
__device__ __align__(128) float d_cmax[Bsz*NHs*32];
__device__ __align__(128) float d_csum[Bsz*NHs*32];
__device__ __align__(128) float d_fbp[32ull*Bsz*NHs*Hsz];
__device__ __align__(128) float d_ctxp[24*Bsz*Hsz];
__device__ __align__(128) float d_yp[24*Bsz*Hsz];
__device__ __align__(128) float d_attn0[Bsz*Hsz];
__device__ __align__(128) float d_gpart[32ull*Bsz*FFs];
__device__ __align__(128) float d_opart[64*Bsz*Hsz];
__device__ __align__(128) float d_hid[Bsz*Hsz];
__device__ __align__(128) float d_pp[24*Bsz*Hsz];

__device__ __align__(128) unsigned d_bar_count;
__device__ __align__(128) unsigned d_gen_rep[32*32];     // 32 replicated lines

typedef unsigned long long ull;

// ---------------- f32x2 packed math ----------------
__device__ __forceinline__ ull ffma2(ull a, ull b, ull c){
  ull d; asm("fma.rn.f32x2 %0, %1, %2, %3;" : "=l"(d) : "l"(a), "l"(b), "l"(c)); return d;
}
__device__ __forceinline__ ull pk2(float lo, float hi){
  ull r; asm("mov.b64 %0, {%1, %2};" : "=l"(r) : "f"(lo), "f"(hi)); return r;
}
__device__ __forceinline__ void upk2(float& lo, float& hi, ull v){
  asm("mov.b64 {%0, %1}, %2;" : "=f"(lo), "=f"(hi) : "l"(v));
}

// ---------------- block reductions ----------------
__device__ __forceinline__ float block_sum(float v, float* red){
  int lane = threadIdx.x & 31, w = threadIdx.x >> 5;
  #pragma unroll
  for (int o = 16; o; o >>= 1) v += __shfl_xor_sync(0xffffffffu, v, o);
  if (lane == 0) red[w] = v;
  __syncthreads();
  float s = (lane < (NT>>5)) ? red[lane] : 0.f;
  #pragma unroll
  for (int o = 16; o; o >>= 1) s += __shfl_xor_sync(0xffffffffu, s, o);
  __syncthreads();
  return s;
}

// ------- grid barrier: replicated gen lines, NO threadfence -------
__device__ __forceinline__ void gsync(){
  __syncthreads();
  if (threadIdx.x == 0){
    unsigned* myline = &d_gen_rep[(blockIdx.x & 31) * 32];
    unsigned gen;
    asm volatile("ld.acquire.gpu.global.u32 %0, [%1];"
                 : "=r"(gen) : "l"(myline) : "memory");
    unsigned arr;
    asm volatile("atom.add.release.gpu.global.u32 %0, [%1], 1;"
                 : "=r"(arr) : "l"(&d_bar_count) : "memory");
    if (arr == NB - 1u){
      asm volatile("st.global.u32 [%0], %1;" :: "l"(&d_bar_count), "r"(0u) : "memory");
      #pragma unroll
      for (int L = 0; L < 32; L++)
        asm volatile("st.release.gpu.global.u32 [%0], %1;"
                     :: "l"(&d_gen_rep[L*32]), "r"(gen + 1u) : "memory");
    } else {
      unsigned g;
      do {
        __nanosleep(128);
        asm volatile("ld.acquire.gpu.global.u32 %0, [%1];"
                     : "=r"(g) : "l"(myline) : "memory");
      } while (g == gen);
    }
  }
  __syncthreads();
}

// padded-u layout: 32-float chunks stored with stride 34 (bank-conflict-free)
#define UPADROW 816            // 768/32*34 floats per head

// =========================== the whole model ===========================
__global__ void __launch_bounds__(NT, 4)
bert_head(const float* __restrict__ f,  const float* __restrict__ mask,
          const float* __restrict__ wq, const float* __restrict__ bq,
          const float* __restrict__ wk, const float* __restrict__ bk,
          const float* __restrict__ wv, const float* __restrict__ bv,
          const float* __restrict__ wo, const float* __restrict__ bo,
          const float* __restrict__ g1, const float* __restrict__ be1,
          const float* __restrict__ w1, const float* __restrict__ b1,
          const float* __restrict__ w2, const float* __restrict__ b2,
          const float* __restrict__ g2, const float* __restrict__ be2,
          const float* __restrict__ wp, const float* __restrict__ bp,
          const float* __restrict__ wm, const float* __restrict__ bm,
          float* __restrict__ out){
  __shared__ __align__(16) float sU[NHs*UPADROW];  // 38.25 KB union scratch
  __shared__ __align__(16) float sS[1024];         // 4 KB
  __shared__ float sred[32];
  float* sf   = sU;
  ull*   sbuf = reinterpret_cast<ull*>(sU);
  ull*   sE   = reinterpret_cast<ull*>(sU);        // reused after scores are done
  const int t = threadIdx.x, bid = blockIdx.x;

  // ---- P1: q0 partials, K-split 24 x j-chunks 6 (W=144) ----
  if (bid < 144){
    int jc = bid % 6, ks = bid / 6;
    int j0 = jc*128, i0 = ks*32;
    #pragma unroll
    for (int k = 0; k < 2; k++){
      int v = t + 256*k;                         // 512 = 16b x 32i
      sf[v] = f[(size_t)(v>>5)*Ssz*Hsz + i0 + (v&31)];
    }
    __syncthreads();
    int j = j0 + (t & 127), bh = t >> 7;
    float binit = (ks == 0) ? bq[j] : 0.f;
    float acc[8];
    #pragma unroll
    for (int bb = 0; bb < 8; bb++) acc[bb] = binit;
    #pragma unroll 8
    for (int i = 0; i < 32; i++){
      float w = wq[(size_t)(i0+i)*Hsz + j];
      #pragma unroll
      for (int bb = 0; bb < 8; bb++)
        acc[bb] = fmaf(sf[(bh*8+bb)*32 + i], w, acc[bb]);
    }
    #pragma unroll
    for (int bb = 0; bb < 8; bb++)
      d_q0p[ks*(Bsz*Hsz) + (bh*8+bb)*Hsz + j] = acc[bb];
  }
  gsync();

  // ---- P2: u[b,h,i] = Wk_h q0[b,h] / 8 ; qbk (W=72) ----
  if (bid < 72){
    int h = bid % 12, ic = bid / 12;
    #pragma unroll
    for (int k = 0; k < 4; k++){
      int v = t + 256*k;                         // b*64+d
      float s = 0.f;
      #pragma unroll
      for (int p = 0; p < 24; p++)
        s += d_q0p[p*(Bsz*Hsz) + (v>>6)*Hsz + h*Dh + (v&63)];
      sf[v] = s;
    }
    __syncthreads();
    if (ic == 0 && t < Bsz){
      float s = 0.f;
      for (int d = 0; d < Dh; d++) s += sf[t*Dh + d]*bk[h*Dh + d];
      d_qbk[t*NHs + h] = s * 0.125f;
    }
    int i = ic*128 + (t & 127), bh = t >> 7;
    const float4* wr = reinterpret_cast<const float4*>(wk + (size_t)i*Hsz + h*Dh);
    float acc[8] = {0,0,0,0,0,0,0,0};
    #pragma unroll
    for (int d4 = 0; d4 < Dh/4; d4++){
      float4 w = wr[d4];
      #pragma unroll
      for (int bb = 0; bb < 8; bb++){
        float4 q = *reinterpret_cast<const float4*>(&sf[(bh*8+bb)*Dh + d4*4]);
        acc[bb] = fmaf(w.x,q.x, fmaf(w.y,q.y, fmaf(w.z,q.z, fmaf(w.w,q.w, acc[bb]))));
      }
    }
    #pragma unroll
    for (int bb = 0; bb < 8; bb++)
      d_u[((bh*8+bb)*NHs + h)*Hsz + i] = acc[bb] * 0.125f;
  }
  gsync();

  // ---- P3': fused scores + chunk softmax + fbar partials (W=512) ----
  {
    int sc = bid & 31, b = bid >> 5;
    const float* ubase = d_u + (size_t)b*NHs*Hsz;
    const float* fbase = f + ((size_t)b*Ssz + sc*32)*Hsz;

    // stage ALL of u[b] into padded smem once
    #pragma unroll
    for (int k = 0; k < NHs*Hsz/NT; k++){
      int idx = t + NT*k;
      sU[(idx>>5)*34 + (idx&31)] = ubase[idx];
    }
    __syncthreads();

    // scores: 32 rows x 8 threads/row; u from padded smem (conflict-free)
    {
      int r = t >> 3, q = t & 7;
      int qhi2 = (q>>2)*17 + (q&3)*4;            // ull offset within 2-chunk group
      ull acc2[NHs];
      #pragma unroll
      for (int h = 0; h < NHs; h++) acc2[h] = 0ull;
      const float* frow = fbase + (size_t)r*Hsz + q*8;
      const ull* ubase2 = reinterpret_cast<const ull*>(sU) + qhi2;
      #pragma unroll 4
      for (int ic = 0; ic < 12; ic++){
        ulonglong2 fv0 = *reinterpret_cast<const ulonglong2*>(frow + ic*64);
        ulonglong2 fv1 = *reinterpret_cast<const ulonglong2*>(frow + ic*64 + 4);
        #pragma unroll
        for (int h = 0; h < NHs; h++){
          const ull* up = ubase2 + h*(UPADROW/2) + ic*34;
          acc2[h] = ffma2(fv0.x, up[0], acc2[h]);
          acc2[h] = ffma2(fv0.y, up[1], acc2[h]);
          acc2[h] = ffma2(fv1.x, up[2], acc2[h]);
          acc2[h] = ffma2(fv1.y, up[3], acc2[h]);
        }
      }
      int srow = sc*32 + r;
      float mv = mask[b*Ssz + srow];
      #pragma unroll
      for (int h = 0; h < NHs; h++){
        float lo, hi; upk2(lo, hi, acc2[h]);
        float v = lo + hi;
        v += __shfl_xor_sync(0xffffffffu, v, 1);
        v += __shfl_xor_sync(0xffffffffu, v, 2);
        v += __shfl_xor_sync(0xffffffffu, v, 4);
        if (q == 0) sS[r*NHs + h] = v + d_qbk[b*NHs + h] + mv;
      }
    }
    __syncthreads();                              // scores done; sU now reusable

    // chunk-local softmax: 12 h x 16 threads, 2 rows each; pack e into sE
    if (t < 192){
      int h = t >> 4, l16 = t & 15;
      float v0 = sS[(l16   )*NHs + h], v1 = sS[(l16+16)*NHs + h];
      float m = fmaxf(v0, v1);
      #pragma unroll
      for (int o = 1; o < 16; o <<= 1) m = fmaxf(m, __shfl_xor_sync(0xffffffffu, m, o));
      float e0 = expf(v0-m), e1 = expf(v1-m);
      float s = e0+e1;
      #pragma unroll
      for (int o = 1; o < 16; o <<= 1) s += __shfl_xor_sync(0xffffffffu, s, o);
      sE[(l16   )*NHs + h] = pk2(e0, e0);
      sE[(l16+16)*NHs + h] = pk2(e1, e1);
      if (l16 == 0){
        d_cmax[(b*NHs + h)*32 + sc] = m;
        d_csum[(b*NHs + h)*32 + sc] = s;
      }
    }
    __syncthreads();

    // fbar partial: i-slice per thread, 2 passes x 6 heads
    if (t < 192){
      const float* fb = fbase + t*4;
      #pragma unroll
      for (int pass = 0; pass < 2; pass++){
        ull acc2[12];
        #pragma unroll
        for (int k = 0; k < 12; k++) acc2[k] = 0ull;
        #pragma unroll 4
        for (int s = 0; s < 32; s++){
          ulonglong2 fv = *reinterpret_cast<const ulonglong2*>(fb + (size_t)s*Hsz);
          #pragma unroll
          for (int hh = 0; hh < 6; hh++){
            ull pp = sE[s*NHs + pass*6 + hh];
            acc2[2*hh]   = ffma2(pp, fv.x, acc2[2*hh]);
            acc2[2*hh+1] = ffma2(pp, fv.y, acc2[2*hh+1]);
          }
        }
        #pragma unroll
        for (int hh = 0; hh < 6; hh++){
          float4 o;
          upk2(o.x, o.y, acc2[2*hh]);
          upk2(o.z, o.w, acc2[2*hh+1]);
          *reinterpret_cast<float4*>(
            &d_fbp[((size_t)(sc*Bsz + b)*NHs + pass*6 + hh)*Hsz + t*4]) = o;
        }
      }
    }
  }
  gsync();

  // ---- P6': rescale+reduce fbar -> ctx partials via wv (W=144) ----
  if (bid < 144){
    int jc = bid % 6, ks = bid / 6;
    int j0 = jc*128, i0 = ks*32, h0 = jc*2;
    if (t < 32){
      int bb = t & 15, hl = t >> 4, h = h0 + hl;
      const float* cm = &d_cmax[(bb*NHs + h)*32];
      const float* cs = &d_csum[(bb*NHs + h)*32];
      float M = cm[0];
      #pragma unroll
      for (int sc = 1; sc < 32; sc++) M = fmaxf(M, cm[sc]);
      float den = 0.f;
      #pragma unroll
      for (int sc = 0; sc < 32; sc++){
        float ex = expf(cm[sc]-M);
        sS[(bb*2+hl)*32 + sc] = ex;
        den += cs[sc]*ex;
      }
      float invd = 1.f/den;
      #pragma unroll
      for (int sc = 0; sc < 32; sc++) sS[(bb*2+hl)*32 + sc] *= invd;
    }
    __syncthreads();
    #pragma unroll
    for (int k = 0; k < 4; k++){
      int v = t + 256*k;                         // 1024 = 16bb x 2hl x 32i
      int bb = v >> 6, hl = (v >> 5) & 1, i = v & 31;
      int h = h0 + hl;
      float s = 0.f;
      #pragma unroll
      for (int sc = 0; sc < 32; sc++)
        s += d_fbp[((size_t)(sc*Bsz + bb)*NHs + h)*Hsz + i0 + i] * sS[(bb*2+hl)*32 + sc];
      sf[v] = s;
    }
    __syncthreads();
    int j = j0 + (t & 127), hl2 = (t & 127) >> 6, bh = t >> 7;
    float acc[8] = {0,0,0,0,0,0,0,0};
    #pragma unroll 8
    for (int i = 0; i < 32; i++){
      float w = wv[(size_t)(i0+i)*Hsz + j];
      #pragma unroll
      for (int bb = 0; bb < 8; bb++)
        acc[bb] = fmaf(sf[(bh*8+bb)*64 + hl2*32 + i], w, acc[bb]);
    }
    #pragma unroll
    for (int bb = 0; bb < 8; bb++)
      d_ctxp[ks*(Bsz*Hsz) + (bh*8+bb)*Hsz + j] = acc[bb];
  }
  gsync();

  // ---- P7: y partials: (ctx+bv) @ wo[:,j], K-split 24 (W=144) ----
  if (bid < 144){
    int jc = bid % 6, ks = bid / 6;
    int j0 = jc*128, i0 = ks*32;
    #pragma unroll
    for (int k = 0; k < 2; k++){
      int v = t + 256*k;                         // 512 = 16b x 32i
      int bb = v >> 5, i = v & 31;
      float s = bv[i0 + i];
      #pragma unroll
      for (int p = 0; p < 24; p++)
        s += d_ctxp[p*(Bsz*Hsz) + bb*Hsz + i0 + i];
      sf[v] = s;
    }
    __syncthreads();
    int j = j0 + (t & 127), bh = t >> 7;
    float acc[8] = {0,0,0,0,0,0,0,0};
    #pragma unroll 8
    for (int i = 0; i < 32; i++){
      float w = wo[(size_t)(i0+i)*Hsz + j];
      #pragma unroll
      for (int bb = 0; bb < 8; bb++)
        acc[bb] = fmaf(sf[(bh*8+bb)*32 + i], w, acc[bb]);
    }
    #pragma unroll
    for (int bb = 0; bb < 8; bb++)
      d_yp[ks*(Bsz*Hsz) + (bh*8+bb)*Hsz + j] = acc[bb];
  }
  gsync();

  // ---- P8: LN1 (W=16) ----
  if (bid < 16){
    int b = bid;
    float yv[3];
    #pragma unroll
    for (int kk = 0; kk < 3; kk++){
      int j = t + 256*kk;
      float y = bo[j] + f[(size_t)b*Ssz*Hsz + j];
      #pragma unroll
      for (int ks = 0; ks < 24; ks++) y += d_yp[ks*(Bsz*Hsz) + b*Hsz + j];
      yv[kk] = y;
    }
    float mu = block_sum(yv[0]+yv[1]+yv[2], sred) * (1.f/Hsz);
    float ss = 0.f;
    #pragma unroll
    for (int kk = 0; kk < 3; kk++){ float d = yv[kk]-mu; ss += d*d; }
    float var = block_sum(ss, sred) * (1.f/Hsz);
    float inv = rsqrtf(var + 1e-12f);
    #pragma unroll
    for (int kk = 0; kk < 3; kk++){
      int j = t + 256*kk;
      d_attn0[b*Hsz + j] = (yv[kk]-mu) * inv * g1[j] + be1[j];
    }
  }
  gsync();

  // ---- P9: FFN1 partials, f32x2 b-pairs, K-split 32 (W=384) ----
  if (bid < 384){
    int mc = bid % 12, is = bid / 12;
    int m = mc*256 + t, i0 = is*24;
    if (t < 192){
      int bp = t / 24, i = t % 24;
      sbuf[t] = pk2(d_attn0[(2*bp)*Hsz + i0 + i], d_attn0[(2*bp+1)*Hsz + i0 + i]);
    }
    __syncthreads();
    ull acc2[8];
    #pragma unroll
    for (int k = 0; k < 8; k++) acc2[k] = 0ull;
    #pragma unroll 8
    for (int i = 0; i < 24; i++){
      float w = w1[(size_t)(i0+i)*FFs + m];
      ull wpk = pk2(w, w);
      #pragma unroll
      for (int bp = 0; bp < 8; bp++)
        acc2[bp] = ffma2(sbuf[bp*24 + i], wpk, acc2[bp]);
    }
    #pragma unroll
    for (int bp = 0; bp < 8; bp++){
      float lo, hi; upk2(lo, hi, acc2[bp]);
      d_gpart[(size_t)(is*Bsz + 2*bp)*FFs + m]   = lo;
      d_gpart[(size_t)(is*Bsz + 2*bp+1)*FFs + m] = hi;
    }
  }
  gsync();

  // ---- P11': fused gelu-reduce + FFN2 partials, K-split 64 (W=192) ----
  if (bid < 192){
    int jc = bid % 3, ms = bid / 3;
    int j = jc*256 + t, m0 = ms*48;
    for (int n = t; n < 384; n += 256){          // 384 = 8bp x 48mm
      int bp = n / 48, mm = n % 48;
      float gv0 = b1[m0+mm], gv1 = gv0;
      #pragma unroll
      for (int is = 0; is < 32; is++){
        gv0 += d_gpart[(size_t)(is*Bsz + 2*bp)*FFs + m0 + mm];
        gv1 += d_gpart[(size_t)(is*Bsz + 2*bp+1)*FFs + m0 + mm];
      }
      gv0 = 0.5f*gv0*(1.f + erff(gv0*0.70710678118654752f));
      gv1 = 0.5f*gv1*(1.f + erff(gv1*0.70710678118654752f));
      sbuf[n] = pk2(gv0, gv1);
    }
    __syncthreads();
    ull acc2[8];
    #pragma unroll
    for (int k = 0; k < 8; k++) acc2[k] = 0ull;
    #pragma unroll 8
    for (int mm = 0; mm < 48; mm++){
      float w = w2[(size_t)(m0+mm)*Hsz + j];
      ull wpk = pk2(w, w);
      #pragma unroll
      for (int bp = 0; bp < 8; bp++)
        acc2[bp] = ffma2(sbuf[bp*48 + mm], wpk, acc2[bp]);
    }
    #pragma unroll
    for (int bp = 0; bp < 8; bp++){
      float lo, hi; upk2(lo, hi, acc2[bp]);
      d_opart[(size_t)(ms*Bsz + 2*bp)*Hsz + j]   = lo;
      d_opart[(size_t)(ms*Bsz + 2*bp+1)*Hsz + j] = hi;
    }
  }
  gsync();

  // ---- P12: LN2 (W=16) ----
  if (bid < 16){
    int b = bid;
    float yv[3];
    #pragma unroll
    for (int kk = 0; kk < 3; kk++){
      int j = t + 256*kk;
      float y = b2[j] + d_attn0[b*Hsz + j];
      #pragma unroll
      for (int ms = 0; ms < 64; ms++) y += d_opart[(size_t)(ms*Bsz + b)*Hsz + j];
      yv[kk] = y;
    }
    float mu = block_sum(yv[0]+yv[1]+yv[2], sred) * (1.f/Hsz);
    float ss = 0.f;
    #pragma unroll
    for (int kk = 0; kk < 3; kk++){ float d = yv[kk]-mu; ss += d*d; }
    float var = block_sum(ss, sred) * (1.f/Hsz);
    float inv = rsqrtf(var + 1e-12f);
    #pragma unroll
    for (int kk = 0; kk < 3; kk++){
      int j = t + 256*kk;
      d_hid[b*Hsz + j] = (yv[kk]-mu) * inv * g2[j] + be2[j];
    }
  }
  gsync();

  // ---- P13: pool partials: hid @ wp + bp, K-split 24 (W=144) ----
  if (bid < 144){
    int jc = bid % 6, ks = bid / 6;
    int j0 = jc*128, i0 = ks*32;
    #pragma unroll
    for (int k = 0; k < 2; k++){
      int v = t + 256*k;                         // 512 = 16b x 32i
      sf[v] = d_hid[(v>>5)*Hsz + i0 + (v&31)];
    }
    __syncthreads();
    int j = j0 + (t & 127), bh = t >> 7;
    float binit = (ks == 0) ? bp[j] : 0.f;
    float acc[8];
    #pragma unroll
    for (int bb = 0; bb < 8; bb++) acc[bb] = binit;
    #pragma unroll 8
    for (int i = 0; i < 32; i++){
      float w = wp[(size_t)(i0+i)*Hsz + j];
      #pragma unroll
      for (int bb = 0; bb < 8; bb++)
        acc[bb] = fmaf(sf[(bh*8+bb)*32 + i], w, acc[bb]);
    }
    #pragma unroll
    for (int bb = 0; bb < 8; bb++)
      d_pp[ks*(Bsz*Hsz) + (bh*8+bb)*Hsz + j] = acc[bb];
  }
  gsync();

  // ---- P14: pooled = tanh(.), cls = pooled @ wm + bm (W=16) ----
  if (bid < 16){
    int b = bid;
    float contrib = 0.f;
    #pragma unroll
    for (int kk = 0; kk < 3; kk++){
      int j = t + 256*kk;
      float y = 0.f;
      #pragma unroll
      for (int ks = 0; ks < 24; ks++) y += d_pp[ks*(Bsz*Hsz) + b*Hsz + j];
      contrib += tanhf(y) * wm[j];
    }
    float c = block_sum(contrib, sred);
    if (t == 0) out[b] = c + bm[0];
  }
}

// ---------------- launch ----------------
extern "C" void kernel_launch(void* const* d_in, const int* in_sizes, int n_in,
                              void* d_out, int out_size){
  (void)in_sizes; (void)n_in; (void)out_size;
  bert_head<<<NB, NT>>>(
    (const float*)d_in[0],  (const float*)d_in[1],
    (const float*)d_in[2],  (const float*)d_in[3],
    (const float*)d_in[4],  (const float*)d_in[5],
    (const float*)d_in[6],  (const float*)d_in[7],
    (const float*)d_in[8],  (const float*)d_in[9],
    (const float*)d_in[10], (const float*)d_in[11],
    (const float*)d_in[12], (const float*)d_in[13],
    (const float*)d_in[14], (const float*)d_in[15],
    (const float*)d_in[16], (const float*)d_in[17],
    (const float*)d_in[18], (const float*)d_in[19],
    (const float*)d_in[20], (const float*)d_in[21],
    (float*)d_out);
}

// round 8
// speedup vs baseline: 1.6453x; 1.6453x over previous
#include <cuda_runtime.h>
#include <math.h>

#define Bsz 16
#define Ssz 1024
#define Hsz 768
#define NHs 12
#define Dh  64
#define FFs 3072
#define NB  256
#define NT  256

// ---------------- scratch (device globals; no allocation) ----------------
__device__ float d_q0p[12*Bsz*Hsz];
__device__ float d_u[Bsz*NHs*Hsz];            // prescaled by 1/8
__device__ float d_qbk[Bsz*NHs];
__device__ float d_cmax[Bsz*NHs*16];          // per-chunk score max
__device__ float d_csum[Bsz*NHs*16];          // per-chunk exp-sum
__device__ float d_fbp[16*Bsz*NHs*Hsz];       // unnormalized fbar partials
__device__ float d_ctxp[12*Bsz*Hsz];
__device__ float d_yp[12*Bsz*Hsz];
__device__ float d_attn0[Bsz*Hsz];
__device__ float d_gpart[16*Bsz*FFs];
__device__ float d_opart[24*Bsz*Hsz];
__device__ float d_hid[Bsz*Hsz];
__device__ float d_pp[12*Bsz*Hsz];

__device__ unsigned d_bar_count = 0;
__device__ unsigned d_bar_gen = 0;

typedef unsigned long long ull;

// ---------------- f32x2 packed math ----------------
__device__ __forceinline__ ull ffma2(ull a, ull b, ull c){
  ull d; asm("fma.rn.f32x2 %0, %1, %2, %3;" : "=l"(d) : "l"(a), "l"(b), "l"(c)); return d;
}
__device__ __forceinline__ ull pk2(float lo, float hi){
  ull r; asm("mov.b64 %0, {%1, %2};" : "=l"(r) : "f"(lo), "f"(hi)); return r;
}
__device__ __forceinline__ void upk2(float& lo, float& hi, ull v){
  asm("mov.b64 {%0, %1}, %2;" : "=f"(lo), "=f"(hi) : "l"(v));
}

// ---------------- block reductions ----------------
__device__ __forceinline__ float block_sum(float v, float* red){
  int lane = threadIdx.x & 31, w = threadIdx.x >> 5;
  #pragma unroll
  for (int o = 16; o; o >>= 1) v += __shfl_xor_sync(0xffffffffu, v, o);
  if (lane == 0) red[w] = v;
  __syncthreads();
  float s = (lane < (NT>>5)) ? red[lane] : 0.f;
  #pragma unroll
  for (int o = 16; o; o >>= 1) s += __shfl_xor_sync(0xffffffffu, s, o);
  __syncthreads();
  return s;
}

// ------- grid barrier (R5-proven: leader atomics + acquire-load polling) -------
__device__ __forceinline__ void gsync(){
  __syncthreads();
  if (threadIdx.x == 0){
    unsigned gen;
    asm volatile("ld.volatile.global.u32 %0, [%1];"
                 : "=r"(gen) : "l"(&d_bar_gen) : "memory");
    unsigned arr;
    asm volatile("atom.add.release.gpu.global.u32 %0, [%1], 1;"
                 : "=r"(arr) : "l"(&d_bar_count) : "memory");
    if (arr == NB - 1u){
      asm volatile("st.global.u32 [%0], %1;" :: "l"(&d_bar_count), "r"(0u) : "memory");
      asm volatile("st.release.gpu.global.u32 [%0], %1;"
                   :: "l"(&d_bar_gen), "r"(gen + 1u) : "memory");
    } else {
      unsigned g;
      do {
        __nanosleep(64);
        asm volatile("ld.acquire.gpu.global.u32 %0, [%1];"
                     : "=r"(g) : "l"(&d_bar_gen) : "memory");
      } while (g == gen);
    }
    __threadfence();   // CCTL.IVALL: invalidate this SM's L1 for post-barrier loads
  }
  __syncthreads();
}

// =========================== the whole model ===========================
__global__ void __launch_bounds__(NT, 2)
bert_head(const float* __restrict__ f,  const float* __restrict__ mask,
          const float* __restrict__ wq, const float* __restrict__ bq,
          const float* __restrict__ wk, const float* __restrict__ bk,
          const float* __restrict__ wv, const float* __restrict__ bv,
          const float* __restrict__ wo, const float* __restrict__ bo,
          const float* __restrict__ g1, const float* __restrict__ be1,
          const float* __restrict__ w1, const float* __restrict__ b1,
          const float* __restrict__ w2, const float* __restrict__ b2,
          const float* __restrict__ g2, const float* __restrict__ be2,
          const float* __restrict__ wp, const float* __restrict__ bp,
          const float* __restrict__ wm, const float* __restrict__ bm,
          float* __restrict__ out){
  __shared__ __align__(16) float sU[NHs*Hsz];    // 36 KB (union scratch)
  __shared__ __align__(16) float sS[1024];       // 4 KB  (scores/probs etc.)
  __shared__ float sred[32];
  float* sf  = sU;
  ull*   sbuf = reinterpret_cast<ull*>(sU);
  const int t = threadIdx.x, bid = blockIdx.x;

  // ---- P1: q0 partials: q0[b,j] = f0[b,:]@wq + bq, K-split 12 (W=72) ----
  if (bid < 72){
    int jc = bid % 6, ks = bid / 6;
    int j0 = jc*128, i0 = ks*64;
    #pragma unroll
    for (int k = 0; k < 4; k++){
      int v = t + 256*k;
      sf[v] = f[(size_t)(v>>6)*Ssz*Hsz + i0 + (v&63)];
    }
    __syncthreads();
    int j = j0 + (t & 127), bh = t >> 7;
    float binit = (ks == 0) ? bq[j] : 0.f;
    float acc[8];
    #pragma unroll
    for (int bb = 0; bb < 8; bb++) acc[bb] = binit;
    #pragma unroll 4
    for (int i = 0; i < 64; i++){
      float w = wq[(size_t)(i0+i)*Hsz + j];
      #pragma unroll
      for (int bb = 0; bb < 8; bb++)
        acc[bb] = fmaf(sf[(bh*8+bb)*64 + i], w, acc[bb]);
    }
    #pragma unroll
    for (int bb = 0; bb < 8; bb++)
      d_q0p[ks*(Bsz*Hsz) + (bh*8+bb)*Hsz + j] = acc[bb];
  }
  gsync();

  // ---- P2: u[b,h,i] = Wk_h q0[b,h] / 8 ; qbk (W=72) ----
  if (bid < 72){
    int h = bid % 12, ic = bid / 12;
    #pragma unroll
    for (int k = 0; k < 4; k++){
      int v = t + 256*k;                         // b*64+d
      float s = 0.f;
      #pragma unroll
      for (int p = 0; p < 12; p++)
        s += d_q0p[p*(Bsz*Hsz) + (v>>6)*Hsz + h*Dh + (v&63)];
      sf[v] = s;
    }
    __syncthreads();
    if (ic == 0 && t < Bsz){
      float s = 0.f;
      for (int d = 0; d < Dh; d++) s += sf[t*Dh + d]*bk[h*Dh + d];
      d_qbk[t*NHs + h] = s * 0.125f;
    }
    int i = ic*128 + (t & 127), bh = t >> 7;
    const float4* wr = reinterpret_cast<const float4*>(wk + (size_t)i*Hsz + h*Dh);
    float acc[8] = {0,0,0,0,0,0,0,0};
    #pragma unroll
    for (int d4 = 0; d4 < Dh/4; d4++){
      float4 w = wr[d4];
      #pragma unroll
      for (int bb = 0; bb < 8; bb++){
        float4 q = *reinterpret_cast<const float4*>(&sf[(bh*8+bb)*Dh + d4*4]);
        acc[bb] = fmaf(w.x,q.x, fmaf(w.y,q.y, fmaf(w.z,q.z, fmaf(w.w,q.w, acc[bb]))));
      }
    }
    #pragma unroll
    for (int bb = 0; bb < 8; bb++)
      d_u[((bh*8+bb)*NHs + h)*Hsz + i] = acc[bb] * 0.125f;
  }
  gsync();

  // ---- P3': fused scores + chunk softmax + fbar partials (W=256) ----
  {
    int sc = bid & 15, b = bid >> 4;
    const float* ubase = d_u + (size_t)b*NHs*Hsz;
    const float* fbase = f + ((size_t)b*Ssz + sc*64)*Hsz;

    // stage ALL of u[b] into smem once (36 KB)
    #pragma unroll
    for (int k = 0; k < NHs*Hsz/NT; k++) sU[t + NT*k] = ubase[t + NT*k];
    __syncthreads();

    // scores: thread (r = s-row, q = i-quarter)
    {
      int r = t >> 2, q = t & 3;
      ull acc2[NHs];
      #pragma unroll
      for (int h = 0; h < NHs; h++) acc2[h] = 0ull;
      const float* frow = fbase + (size_t)r*Hsz + q*8;
      #pragma unroll 4
      for (int ic = 0; ic < 24; ic++){
        ulonglong2 fv0 = *reinterpret_cast<const ulonglong2*>(frow + ic*32);
        ulonglong2 fv1 = *reinterpret_cast<const ulonglong2*>(frow + ic*32 + 4);
        #pragma unroll
        for (int h = 0; h < NHs; h++){
          const ull* up = reinterpret_cast<const ull*>(&sU[h*Hsz + ic*32 + q*8]);
          acc2[h] = ffma2(fv0.x, up[0], acc2[h]);
          acc2[h] = ffma2(fv0.y, up[1], acc2[h]);
          acc2[h] = ffma2(fv1.x, up[2], acc2[h]);
          acc2[h] = ffma2(fv1.y, up[3], acc2[h]);
        }
      }
      int srow = sc*64 + r;
      float mv = mask[b*Ssz + srow];
      #pragma unroll
      for (int h = 0; h < NHs; h++){
        float lo, hi; upk2(lo, hi, acc2[h]);
        float v = lo + hi;
        v += __shfl_xor_sync(0xffffffffu, v, 1);
        v += __shfl_xor_sync(0xffffffffu, v, 2);
        if (q == 0) sS[r*NHs + h] = v + d_qbk[b*NHs + h] + mv;
      }
    }
    __syncthreads();

    // chunk-local softmax: 12 h x 16 threads, 4 s each
    if (t < 192){
      int h = t >> 4, l16 = t & 15;
      float v0 = sS[(l16   )*NHs + h], v1 = sS[(l16+16)*NHs + h];
      float v2 = sS[(l16+32)*NHs + h], v3 = sS[(l16+48)*NHs + h];
      float m = fmaxf(fmaxf(v0,v1), fmaxf(v2,v3));
      #pragma unroll
      for (int o = 1; o < 16; o <<= 1) m = fmaxf(m, __shfl_xor_sync(0xffffffffu, m, o));
      float e0 = expf(v0-m), e1 = expf(v1-m), e2 = expf(v2-m), e3 = expf(v3-m);
      float s = e0+e1+e2+e3;
      #pragma unroll
      for (int o = 1; o < 16; o <<= 1) s += __shfl_xor_sync(0xffffffffu, s, o);
      sS[(l16   )*NHs + h] = e0; sS[(l16+16)*NHs + h] = e1;
      sS[(l16+32)*NHs + h] = e2; sS[(l16+48)*NHs + h] = e3;
      if (l16 == 0){
        d_cmax[(b*NHs + h)*16 + sc] = m;
        d_csum[(b*NHs + h)*16 + sc] = s;
      }
    }
    __syncthreads();

    // fbar partial: i-slice per thread, f re-read from hot L2
    if (t < 192){
      ull acc2[2*NHs];
      #pragma unroll
      for (int k = 0; k < 2*NHs; k++) acc2[k] = 0ull;
      const float* fb = fbase + t*4;
      #pragma unroll 4
      for (int s = 0; s < 64; s++){
        ulonglong2 fv = *reinterpret_cast<const ulonglong2*>(fb + (size_t)s*Hsz);
        #pragma unroll
        for (int h = 0; h < NHs; h++){
          float e = sS[s*NHs + h];
          ull pp = pk2(e, e);
          acc2[2*h]   = ffma2(pp, fv.x, acc2[2*h]);
          acc2[2*h+1] = ffma2(pp, fv.y, acc2[2*h+1]);
        }
      }
      #pragma unroll
      for (int h = 0; h < NHs; h++){
        float4 o;
        upk2(o.x, o.y, acc2[2*h]);
        upk2(o.z, o.w, acc2[2*h+1]);
        *reinterpret_cast<float4*>(
          &d_fbp[((size_t)(sc*Bsz + b)*NHs + h)*Hsz + t*4]) = o;
      }
    }
  }
  gsync();

  // ---- P6': rescale+reduce fbar -> ctx partials via wv (W=72) ----
  if (bid < 72){
    int jc = bid % 6, ks = bid / 6;
    int j0 = jc*128, i0 = ks*64, h0 = jc*2;
    if (t < 32){
      int bb = t & 15, hl = t >> 4, h = h0 + hl;
      const float* cm = &d_cmax[(bb*NHs + h)*16];
      const float* cs = &d_csum[(bb*NHs + h)*16];
      float M = cm[0];
      #pragma unroll
      for (int sc = 1; sc < 16; sc++) M = fmaxf(M, cm[sc]);
      float wv_[16]; float den = 0.f;
      #pragma unroll
      for (int sc = 0; sc < 16; sc++){ wv_[sc] = expf(cm[sc]-M); den += cs[sc]*wv_[sc]; }
      float invd = 1.f/den;
      #pragma unroll
      for (int sc = 0; sc < 16; sc++) sS[(bb*2+hl)*16 + sc] = wv_[sc]*invd;
    }
    __syncthreads();
    #pragma unroll
    for (int k = 0; k < 8; k++){
      int v = t + 256*k;
      int bb = v>>7, hl = (v>>6)&1, i = v&63;
      int h = h0 + hl;
      float s = 0.f;
      #pragma unroll
      for (int sc = 0; sc < 16; sc++)
        s += d_fbp[((size_t)(sc*Bsz + bb)*NHs + h)*Hsz + i0 + i] * sS[(bb*2+hl)*16 + sc];
      sf[v] = s;
    }
    __syncthreads();
    int j = j0 + (t & 127), hl = (t & 127) >> 6, bh = t >> 7;
    float acc[8] = {0,0,0,0,0,0,0,0};
    #pragma unroll 4
    for (int i = 0; i < 64; i++){
      float w = wv[(size_t)(i0+i)*Hsz + j];
      #pragma unroll
      for (int bb = 0; bb < 8; bb++)
        acc[bb] = fmaf(sf[(bh*8+bb)*128 + hl*64 + i], w, acc[bb]);
    }
    #pragma unroll
    for (int bb = 0; bb < 8; bb++)
      d_ctxp[ks*(Bsz*Hsz) + (bh*8+bb)*Hsz + j] = acc[bb];
  }
  gsync();

  // ---- P7: y partials: (ctx+bv) @ wo[:,j], K-split 12 (W=72) ----
  if (bid < 72){
    int jc = bid % 6, ks = bid / 6;
    int j0 = jc*128, i0 = ks*64;
    #pragma unroll
    for (int k = 0; k < 4; k++){
      int v = t + 256*k;
      int bb = v>>6, i = v&63;
      float s = bv[i0 + i];
      #pragma unroll
      for (int p = 0; p < 12; p++)
        s += d_ctxp[p*(Bsz*Hsz) + bb*Hsz + i0 + i];
      sf[v] = s;
    }
    __syncthreads();
    int j = j0 + (t & 127), bh = t >> 7;
    float acc[8] = {0,0,0,0,0,0,0,0};
    #pragma unroll 4
    for (int i = 0; i < 64; i++){
      float w = wo[(size_t)(i0+i)*Hsz + j];
      #pragma unroll
      for (int bb = 0; bb < 8; bb++)
        acc[bb] = fmaf(sf[(bh*8+bb)*64 + i], w, acc[bb]);
    }
    #pragma unroll
    for (int bb = 0; bb < 8; bb++)
      d_yp[ks*(Bsz*Hsz) + (bh*8+bb)*Hsz + j] = acc[bb];
  }
  gsync();

  // ---- P8: LN1 (W=16) ----
  if (bid < 16){
    int b = bid;
    float yv[3];
    #pragma unroll
    for (int kk = 0; kk < 3; kk++){
      int j = t + 256*kk;
      float y = bo[j] + f[(size_t)b*Ssz*Hsz + j];
      #pragma unroll
      for (int ks = 0; ks < 12; ks++) y += d_yp[ks*(Bsz*Hsz) + b*Hsz + j];
      yv[kk] = y;
    }
    float mu = block_sum(yv[0]+yv[1]+yv[2], sred) * (1.f/Hsz);
    float ss = 0.f;
    #pragma unroll
    for (int kk = 0; kk < 3; kk++){ float d = yv[kk]-mu; ss += d*d; }
    float var = block_sum(ss, sred) * (1.f/Hsz);
    float inv = rsqrtf(var + 1e-12f);
    #pragma unroll
    for (int kk = 0; kk < 3; kk++){
      int j = t + 256*kk;
      d_attn0[b*Hsz + j] = (yv[kk]-mu) * inv * g1[j] + be1[j];
    }
  }
  gsync();

  // ---- P9: FFN1 partials, f32x2 b-pairs, K-split 16 (W=192) ----
  if (bid < 192){
    int mc = bid % 12, is = bid / 12;
    int m = mc*256 + t, i0 = is*48;
    for (int n = t; n < 8*48; n += 256){
      int bp = n / 48, i = n % 48;
      sbuf[n] = pk2(d_attn0[(2*bp)*Hsz + i0 + i], d_attn0[(2*bp+1)*Hsz + i0 + i]);
    }
    __syncthreads();
    ull acc2[8];
    #pragma unroll
    for (int k = 0; k < 8; k++) acc2[k] = 0ull;
    #pragma unroll 4
    for (int i = 0; i < 48; i++){
      float w = w1[(size_t)(i0+i)*FFs + m];
      ull wpk = pk2(w, w);
      #pragma unroll
      for (int bp = 0; bp < 8; bp++)
        acc2[bp] = ffma2(sbuf[bp*48 + i], wpk, acc2[bp]);
    }
    #pragma unroll
    for (int bp = 0; bp < 8; bp++){
      float lo, hi; upk2(lo, hi, acc2[bp]);
      d_gpart[(size_t)(is*Bsz + 2*bp)*FFs + m]   = lo;
      d_gpart[(size_t)(is*Bsz + 2*bp+1)*FFs + m] = hi;
    }
  }
  gsync();

  // ---- P11': fused gelu-reduce + FFN2 partials, K-split 24 (W=72) ----
  if (bid < 72){
    int jc = bid % 3, ms = bid / 3;
    int j = jc*256 + t, m0 = ms*128;
    for (int n = t; n < 1024; n += 256){         // 1024 = 8bp x 128mm
      int bp = n >> 7, mm = n & 127;
      float gv0 = b1[m0+mm], gv1 = gv0;
      #pragma unroll
      for (int is = 0; is < 16; is++){
        gv0 += d_gpart[(size_t)(is*Bsz + 2*bp)*FFs + m0 + mm];
        gv1 += d_gpart[(size_t)(is*Bsz + 2*bp+1)*FFs + m0 + mm];
      }
      gv0 = 0.5f*gv0*(1.f + erff(gv0*0.70710678118654752f));
      gv1 = 0.5f*gv1*(1.f + erff(gv1*0.70710678118654752f));
      sbuf[n] = pk2(gv0, gv1);
    }
    __syncthreads();
    ull acc2[8];
    #pragma unroll
    for (int k = 0; k < 8; k++) acc2[k] = 0ull;
    #pragma unroll 4
    for (int mm = 0; mm < 128; mm++){
      float w = w2[(size_t)(m0+mm)*Hsz + j];
      ull wpk = pk2(w, w);
      #pragma unroll
      for (int bp = 0; bp < 8; bp++)
        acc2[bp] = ffma2(sbuf[bp*128 + mm], wpk, acc2[bp]);
    }
    #pragma unroll
    for (int bp = 0; bp < 8; bp++){
      float lo, hi; upk2(lo, hi, acc2[bp]);
      d_opart[(size_t)(ms*Bsz + 2*bp)*Hsz + j]   = lo;
      d_opart[(size_t)(ms*Bsz + 2*bp+1)*Hsz + j] = hi;
    }
  }
  gsync();

  // ---- P12: LN2 (W=16) ----
  if (bid < 16){
    int b = bid;
    float yv[3];
    #pragma unroll
    for (int kk = 0; kk < 3; kk++){
      int j = t + 256*kk;
      float y = b2[j] + d_attn0[b*Hsz + j];
      #pragma unroll
      for (int ms = 0; ms < 24; ms++) y += d_opart[(size_t)(ms*Bsz + b)*Hsz + j];
      yv[kk] = y;
    }
    float mu = block_sum(yv[0]+yv[1]+yv[2], sred) * (1.f/Hsz);
    float ss = 0.f;
    #pragma unroll
    for (int kk = 0; kk < 3; kk++){ float d = yv[kk]-mu; ss += d*d; }
    float var = block_sum(ss, sred) * (1.f/Hsz);
    float inv = rsqrtf(var + 1e-12f);
    #pragma unroll
    for (int kk = 0; kk < 3; kk++){
      int j = t + 256*kk;
      d_hid[b*Hsz + j] = (yv[kk]-mu) * inv * g2[j] + be2[j];
    }
  }
  gsync();

  // ---- P13: pool partials: hid @ wp + bp, K-split 12 (W=72) ----
  if (bid < 72){
    int jc = bid % 6, ks = bid / 6;
    int j0 = jc*128, i0 = ks*64;
    #pragma unroll
    for (int k = 0; k < 4; k++){
      int v = t + 256*k;
      sf[v] = d_hid[(v>>6)*Hsz + i0 + (v&63)];
    }
    __syncthreads();
    int j = j0 + (t & 127), bh = t >> 7;
    float binit = (ks == 0) ? bp[j] : 0.f;
    float acc[8];
    #pragma unroll
    for (int bb = 0; bb < 8; bb++) acc[bb] = binit;
    #pragma unroll 4
    for (int i = 0; i < 64; i++){
      float w = wp[(size_t)(i0+i)*Hsz + j];
      #pragma unroll
      for (int bb = 0; bb < 8; bb++)
        acc[bb] = fmaf(sf[(bh*8+bb)*64 + i], w, acc[bb]);
    }
    #pragma unroll
    for (int bb = 0; bb < 8; bb++)
      d_pp[ks*(Bsz*Hsz) + (bh*8+bb)*Hsz + j] = acc[bb];
  }
  gsync();

  // ---- P14: pooled = tanh(.), cls = pooled @ wm + bm (W=16) ----
  if (bid < 16){
    int b = bid;
    float contrib = 0.f;
    #pragma unroll
    for (int kk = 0; kk < 3; kk++){
      int j = t + 256*kk;
      float y = 0.f;
      #pragma unroll
      for (int ks = 0; ks < 12; ks++) y += d_pp[ks*(Bsz*Hsz) + b*Hsz + j];
      contrib += tanhf(y) * wm[j];
    }
    float c = block_sum(contrib, sred);
    if (t == 0) out[b] = c + bm[0];
  }
}

// ---------------- launch ----------------
extern "C" void kernel_launch(void* const* d_in, const int* in_sizes, int n_in,
                              void* d_out, int out_size){
  (void)in_sizes; (void)n_in; (void)out_size;
  bert_head<<<NB, NT>>>(
    (const float*)d_in[0],  (const float*)d_in[1],
    (const float*)d_in[2],  (const float*)d_in[3],
    (const float*)d_in[4],  (const float*)d_in[5],
    (const float*)d_in[6],  (const float*)d_in[7],
    (const float*)d_in[8],  (const float*)d_in[9],
    (const float*)d_in[10], (const float*)d_in[11],
    (const float*)d_in[12], (const float*)d_in[13],
    (const float*)d_in[14], (const float*)d_in[15],
    (const float*)d_in[16], (const float*)d_in[17],
    (const float*)d_in[18], (const float*)d_in[19],
    (const float*)d_in[20], (const float*)d_in[21],
    (float*)d_out);
}